// round 1
// baseline (speedup 1.0000x reference)
#include <cuda_runtime.h>
#include <math.h>

// Problem constants
#define Bc  4
#define Tc  4096
#define Dc  1024
#define Hc  16
#define HDc 64
#define Kc  32

// Scratch (static device arrays — no runtime allocation allowed)
__device__ float g_qkv[(size_t)Bc * Tc * 3 * Dc];           // 192 MiB: (B,T,3,H,HD)
__device__ float g_mid[(size_t)Bc * Tc * Dc];               // 64 MiB : (B,T,D) pre-W_out
__device__ float g_spec[(size_t)3 * Bc * Hc * Kc * HDc];    // q/k/v spec (s,bh,k,d)
__device__ float g_ws[(size_t)Bc * Hc * Kc * HDc];          // response * v_spec

// ---------------------------------------------------------------------------
// GEMM (NT): C[M,N] = A[M,Kd] * Bm[N,Kd]^T, all row-major fp32.
// 128x128 block tile, K-tile 8, 256 threads, 8x8 accumulators per thread.
// M,N multiples of 128; Kd multiple of 8.
// ---------------------------------------------------------------------------
__global__ __launch_bounds__(256) void gemm_nt_128(
    const float* __restrict__ A, const float* __restrict__ Bm,
    float* __restrict__ C, int M, int N, int Kd)
{
    __shared__ float As[8][128];
    __shared__ float Bs[8][128];
    const int tid = threadIdx.x;
    const int row0 = blockIdx.y * 128;
    const int col0 = blockIdx.x * 128;
    const int lrow = tid >> 1;            // 0..127
    const int lk   = (tid & 1) * 4;       // 0 or 4
    const int ty   = tid >> 4;            // 0..15
    const int tx   = tid & 15;            // 0..15

    float acc[8][8];
#pragma unroll
    for (int i = 0; i < 8; i++)
#pragma unroll
        for (int j = 0; j < 8; j++) acc[i][j] = 0.f;

    const float* Ap = A  + (size_t)row0 * Kd;
    const float* Bp = Bm + (size_t)col0 * Kd;

    for (int k0 = 0; k0 < Kd; k0 += 8) {
        float4 av = *(const float4*)(Ap + (size_t)lrow * Kd + k0 + lk);
        float4 bv = *(const float4*)(Bp + (size_t)lrow * Kd + k0 + lk);
        As[lk + 0][lrow] = av.x; As[lk + 1][lrow] = av.y;
        As[lk + 2][lrow] = av.z; As[lk + 3][lrow] = av.w;
        Bs[lk + 0][lrow] = bv.x; Bs[lk + 1][lrow] = bv.y;
        Bs[lk + 2][lrow] = bv.z; Bs[lk + 3][lrow] = bv.w;
        __syncthreads();
#pragma unroll
        for (int kk = 0; kk < 8; kk++) {
            float ra[8], rb[8];
#pragma unroll
            for (int i = 0; i < 8; i++) ra[i] = As[kk][ty * 8 + i];
#pragma unroll
            for (int j = 0; j < 8; j++) rb[j] = Bs[kk][tx * 8 + j];
#pragma unroll
            for (int i = 0; i < 8; i++)
#pragma unroll
                for (int j = 0; j < 8; j++)
                    acc[i][j] = fmaf(ra[i], rb[j], acc[i][j]);
        }
        __syncthreads();
    }

#pragma unroll
    for (int i = 0; i < 8; i++) {
        float* Cr = C + (size_t)(row0 + ty * 8 + i) * N + col0 + tx * 8;
#pragma unroll
        for (int j = 0; j < 8; j += 4) {
            *(float4*)(Cr + j) = make_float4(acc[i][j], acc[i][j + 1],
                                             acc[i][j + 2], acc[i][j + 3]);
        }
    }
}

// ---------------------------------------------------------------------------
// qm = mean_t q[b,h,t,:]  then tiny MLP -> pulse_widths[b,h]
// One block per (b,h), 256 threads.
// q[b,h,t,d] = g_qkv[(b*T+t)*3072 + 0*1024 + h*64 + d]
// ---------------------------------------------------------------------------
__global__ __launch_bounds__(256) void qm_pulse_kernel(
    const float* __restrict__ W1, const float* __restrict__ b1,
    const float* __restrict__ W2, const float* __restrict__ b2,
    float* __restrict__ out_pulse)
{
    const int bh = blockIdx.x;
    const int b = bh >> 4, h = bh & 15;
    const int tid = threadIdx.x;
    const int d = tid & 63, chunk = tid >> 6;   // 4 chunks of 1024 t's

    const float* base = g_qkv + (size_t)b * Tc * 3072 + h * 64 + d;
    float s = 0.f;
    const int t0 = chunk * 1024;
    for (int t = t0; t < t0 + 1024; t++)
        s += base[(size_t)t * 3072];

    __shared__ float part[256];
    __shared__ float qm[64];
    __shared__ float h1s[32];
    part[tid] = s;
    __syncthreads();
    if (tid < 64)
        qm[tid] = (part[tid] + part[tid + 64] + part[tid + 128] + part[tid + 192])
                  * (1.0f / Tc);
    __syncthreads();
    if (tid < 32) {
        float acc = b1[tid];
        for (int dd = 0; dd < 64; dd++)
            acc = fmaf(qm[dd], W1[tid * 64 + dd], acc);
        h1s[tid] = acc / (1.f + expf(-acc));        // silu
        float p = h1s[tid] * W2[tid];
#pragma unroll
        for (int off = 16; off; off >>= 1)
            p += __shfl_down_sync(0xffffffffu, p, off);
        if (tid == 0) {
            float x = p + b2[0];
            float sp = (x > 20.f) ? x : log1pf(expf(x));  // softplus
            out_pulse[bh] = 4.0f + sp;
        }
    }
}

// ---------------------------------------------------------------------------
// Spectral projection: spec_s[b,h,k,d] = sum_t qkv_s[b,h,t,d] * sb[b,t,k]
// One block per (bh, s). 256 threads, each owns (k, 8 d's). T-tiles of 64.
// ---------------------------------------------------------------------------
__global__ __launch_bounds__(256) void spec_kernel(const float* __restrict__ sb)
{
    const int bh = blockIdx.x, s = blockIdx.y;
    const int b = bh >> 4, h = bh & 15;
    const int tid = threadIdx.x;
    const int k = tid >> 3;            // 0..31
    const int d0 = (tid & 7) * 8;      // 0..56

    __shared__ float sbs[64][33];
    __shared__ float qs[64][65];
    float acc[8];
#pragma unroll
    for (int i = 0; i < 8; i++) acc[i] = 0.f;

    const float* qbase = g_qkv + (size_t)b * Tc * 3072 + s * 1024 + h * 64;
    const float* sbase = sb + (size_t)b * Tc * 32;

    for (int t0 = 0; t0 < Tc; t0 += 64) {
#pragma unroll
        for (int i = 0; i < 2; i++) {                 // sb tile 64x32
            int e = tid + i * 256;
            int tt = e >> 3, k4 = (e & 7) * 4;
            float4 v = *(const float4*)(sbase + (size_t)(t0 + tt) * 32 + k4);
            sbs[tt][k4 + 0] = v.x; sbs[tt][k4 + 1] = v.y;
            sbs[tt][k4 + 2] = v.z; sbs[tt][k4 + 3] = v.w;
        }
#pragma unroll
        for (int i = 0; i < 4; i++) {                 // q/k/v tile 64x64
            int e = tid + i * 256;
            int tt = e >> 4, d4 = (e & 15) * 4;
            float4 v = *(const float4*)(qbase + (size_t)(t0 + tt) * 3072 + d4);
            qs[tt][d4 + 0] = v.x; qs[tt][d4 + 1] = v.y;
            qs[tt][d4 + 2] = v.z; qs[tt][d4 + 3] = v.w;
        }
        __syncthreads();
        for (int t = 0; t < 64; t++) {
            float sv = sbs[t][k];
#pragma unroll
            for (int i = 0; i < 8; i++)
                acc[i] = fmaf(sv, qs[t][d0 + i], acc[i]);
        }
        __syncthreads();
    }
    float* outp = g_spec + ((size_t)(s * (Bc * Hc) + bh) * Kc + k) * HDc + d0;
#pragma unroll
    for (int i = 0; i < 8; i++) outp[i] = acc[i];
}

// ---------------------------------------------------------------------------
// attn_spec + FitzHugh-Nagumo dynamics (constant along HD -> scalar ODE)
// One thread per (b,h,k). Also produces ws = response * v_spec.
// ---------------------------------------------------------------------------
__global__ void soliton_kernel(
    const float* __restrict__ d_a, const float* __restrict__ d_b,
    const float* __restrict__ filt, float* __restrict__ out_resp)
{
    const int idx = blockIdx.x * blockDim.x + threadIdx.x;   // 0..2047
    if (idx >= Bc * Hc * Kc) return;
    const int bh = idx >> 5, k = idx & 31;
    const int h = bh & 15;

    const size_t specN = (size_t)Bc * Hc * Kc * HDc;
    const float* qv = g_spec + (size_t)idx * 64;
    const float* kv = g_spec + specN + (size_t)idx * 64;
    float dot = 0.f;
#pragma unroll
    for (int d = 0; d < 64; d++) dot = fmaf(qv[d], kv[d], dot);

    float f = 1.f / (1.f + expf(-filt[h * 32 + k]));
    float stim = dot * 0.125f * f;                 // /sqrt(64) * sigmoid(filter)

    const float a = d_a[0], bb = d_b[0];
    float scale = fmaxf(fabsf(stim), 1e-6f);
    float sn = stim / scale;
    float I = (fabsf(stim) > 0.5f) ? sn : sn * 0.1f;
    float v = 0.f, w = 0.f;
    const float dt = 0.2f;
#pragma unroll
    for (int s = 0; s < 5; s++) {
        float dv = v - v * v * v * (1.f / 3.f) - w + I;
        float dw = (v + a - bb * w) * 10.f;        // /TAU, TAU=0.1
        v = fminf(fmaxf(v + dt * dv, -3.f), 3.f);
        w = fminf(fmaxf(w + dt * dw, -3.f), 3.f);
    }
    float resp = v * scale;                         // == mean over HD (constant)
    out_resp[idx] = resp;

    const float* vv = g_spec + 2 * specN + (size_t)idx * 64;
    float* ws = g_ws + (size_t)idx * 64;
#pragma unroll
    for (int d = 0; d < 64; d++) ws[d] = resp * vv[d];
}

// ---------------------------------------------------------------------------
// Recombine: mid[b,t,h*64+d] = sum_k sb[b,t,k] * ws[b,h,k,d]
// Block per (bh, t-tile of 128). 256 threads.
// ---------------------------------------------------------------------------
__global__ __launch_bounds__(256) void recombine_kernel(const float* __restrict__ sb)
{
    const int bh = blockIdx.x;
    const int b = bh >> 4, h = bh & 15;
    const int t0 = blockIdx.y * 128;
    const int tid = threadIdx.x;

    __shared__ float ws_s[32][65];
    __shared__ float sbs[128][33];

#pragma unroll
    for (int i = 0; i < 2; i++) {                  // ws 32x64
        int e = tid + i * 256;
        int kk = e >> 4, d4 = (e & 15) * 4;
        float4 v = *(const float4*)(g_ws + ((size_t)bh * 32 + kk) * 64 + d4);
        ws_s[kk][d4 + 0] = v.x; ws_s[kk][d4 + 1] = v.y;
        ws_s[kk][d4 + 2] = v.z; ws_s[kk][d4 + 3] = v.w;
    }
    const float* sbase = sb + (size_t)b * Tc * 32;
#pragma unroll
    for (int i = 0; i < 4; i++) {                  // sb 128x32
        int e = tid + i * 256;
        int tt = e >> 3, k4 = (e & 7) * 4;
        float4 v = *(const float4*)(sbase + (size_t)(t0 + tt) * 32 + k4);
        sbs[tt][k4 + 0] = v.x; sbs[tt][k4 + 1] = v.y;
        sbs[tt][k4 + 2] = v.z; sbs[tt][k4 + 3] = v.w;
    }
    __syncthreads();

    for (int e = tid; e < 128 * 64; e += 256) {
        int t = e >> 6, d = e & 63;
        float acc = 0.f;
#pragma unroll
        for (int k = 0; k < 32; k++)
            acc = fmaf(sbs[t][k], ws_s[k][d], acc);
        g_mid[(size_t)(b * Tc + t0 + t) * Dc + h * 64 + d] = acc;
    }
}

// ---------------------------------------------------------------------------
// Launch
// Inputs (metadata order): x, spectral_basis, W_qkv, W_out, a, b,
//                          W1, b1, W2, b2, spectral_filter
// Outputs: out (B*T*D) ++ pulse_widths (B*H) ++ response (B*H*K)
// ---------------------------------------------------------------------------
extern "C" void kernel_launch(void* const* d_in, const int* in_sizes, int n_in,
                              void* d_out, int out_size)
{
    const float* x    = (const float*)d_in[0];
    const float* sb   = (const float*)d_in[1];
    const float* Wqkv = (const float*)d_in[2];
    const float* Wout = (const float*)d_in[3];
    const float* a    = (const float*)d_in[4];
    const float* b    = (const float*)d_in[5];
    const float* W1   = (const float*)d_in[6];
    const float* b1   = (const float*)d_in[7];
    const float* W2   = (const float*)d_in[8];
    const float* b2   = (const float*)d_in[9];
    const float* filt = (const float*)d_in[10];

    float* out       = (float*)d_out;
    float* out_pulse = out + (size_t)Bc * Tc * Dc;
    float* out_resp  = out_pulse + Bc * Hc;

    float *pqkv = nullptr, *pmid = nullptr;
    cudaGetSymbolAddress((void**)&pqkv, g_qkv);
    cudaGetSymbolAddress((void**)&pmid, g_mid);

    // 1) QKV projection: (16384 x 1024) @ (3072 x 1024)^T
    gemm_nt_128<<<dim3(3 * Dc / 128, Bc * Tc / 128), 256>>>(
        x, Wqkv, pqkv, Bc * Tc, 3 * Dc, Dc);

    // 2) Pulse widths (q mean + MLP)
    qm_pulse_kernel<<<Bc * Hc, 256>>>(W1, b1, W2, b2, out_pulse);

    // 3) Spectral projections for q, k, v
    spec_kernel<<<dim3(Bc * Hc, 3), 256>>>(sb);

    // 4) attn_spec + soliton dynamics + ws = resp * v_spec
    soliton_kernel<<<(Bc * Hc * Kc + 255) / 256, 256>>>(a, b, filt, out_resp);

    // 5) Recombine back to time domain -> mid (B,T,D)
    recombine_kernel<<<dim3(Bc * Hc, Tc / 128), 256>>>(sb);

    // 6) Output projection: (16384 x 1024) @ (1024 x 1024)^T
    gemm_nt_128<<<dim3(Dc / 128, Bc * Tc / 128), 256>>>(
        pmid, Wout, out, Bc * Tc, Dc, Dc);
}

// round 4
// speedup vs baseline: 2.2605x; 2.2605x over previous
#include <cuda_runtime.h>
#include <cuda_bf16.h>
#include <math.h>
#include <stdint.h>

// Problem constants
#define Bc  4
#define Tc  4096
#define Dc  1024
#define Hc  16
#define HDc 64
#define Kc  32

// ---------------- scratch (static device arrays) ----------------
__device__ float g_qkv[(size_t)Bc * Tc * 3 * Dc];           // (B,T,3,H,HD) fp32
__device__ float g_spec[(size_t)3 * Bc * Hc * Kc * HDc];    // q/k/v spectral
__device__ float g_ws[(size_t)Bc * Hc * Kc * HDc];          // response * v_spec
__device__ __nv_bfloat16 g_xhi[(size_t)Bc * Tc * Dc];
__device__ __nv_bfloat16 g_xlo[(size_t)Bc * Tc * Dc];
__device__ __nv_bfloat16 g_wqhi[(size_t)3 * Dc * Dc];
__device__ __nv_bfloat16 g_wqlo[(size_t)3 * Dc * Dc];
__device__ __nv_bfloat16 g_wohi[(size_t)Dc * Dc];
__device__ __nv_bfloat16 g_wolo[(size_t)Dc * Dc];
__device__ __nv_bfloat16 g_mhi[(size_t)Bc * Tc * Dc];
__device__ __nv_bfloat16 g_mlo[(size_t)Bc * Tc * Dc];

__device__ __forceinline__ uint32_t smem_u32(const void* p) {
    uint32_t a;
    asm("{ .reg .u64 t; cvta.to.shared.u64 t, %1; cvt.u32.u64 %0, t; }"
        : "=r"(a) : "l"(p));
    return a;
}

// ---------------------------------------------------------------------------
// Tensor-core GEMM (NT) via mma.sync (HMMA): C[M,N] = A*B^T.
// A,B given as bf16 hi/lo split pairs, row-major [rows, 1024].
// C = Ahi*Bhi^T + Ahi*Blo^T + Alo*Bhi^T   (fp32 accum)
// 128x128 CTA tile, K-tile 32, cp.async double buffer, 8 warps (2x4),
// each warp 64x32 via m16n8k16.
// SMEM tiles: 128 rows x 32 bf16, rows padded to 80B (conflict-free ldmatrix).
// ---------------------------------------------------------------------------
#define KT      32
#define RB      80                 // padded row bytes (32 bf16 = 64B data)
#define TILE_B  (128 * RB)         // 10240 B per tile
#define STAGE_B (4 * TILE_B)       // Ahi,Alo,Bhi,Blo per stage

__global__ void __launch_bounds__(256) gemm_mma(
    const __nv_bfloat16* __restrict__ Ahi, const __nv_bfloat16* __restrict__ Alo,
    const __nv_bfloat16* __restrict__ Bhi, const __nv_bfloat16* __restrict__ Blo,
    float* __restrict__ C, int M, int N)
{
    extern __shared__ char smem[];
    const int Kd = 1024;
    const uint32_t sbase = smem_u32(smem);
    const int tid = threadIdx.x, wid = tid >> 5, lane = tid & 31;
    const int row0 = blockIdx.y * 128, col0 = blockIdx.x * 128;
    const int wm = wid >> 2, wn = wid & 3;           // warp tile: 64m x 32n

    const __nv_bfloat16* s0 = Ahi + (size_t)row0 * Kd;
    const __nv_bfloat16* s1 = Alo + (size_t)row0 * Kd;
    const __nv_bfloat16* s2 = Bhi + (size_t)col0 * Kd;
    const __nv_bfloat16* s3 = Blo + (size_t)col0 * Kd;

    // per-thread cp.async mapping: 2 chunks per tile (512 chunks / 256 thr)
    const int e0 = tid, e1 = tid + 256;
    const int r0c = e0 >> 2, c0c = e0 & 3;           // row 0..63,  chunk
    const int r1c = e1 >> 2, c1c = e1 & 3;           // row 64..127, chunk

#define LOAD_STAGE(kt, buf)                                                   \
    do {                                                                      \
        uint32_t db = sbase + (buf) * STAGE_B;                                \
        const __nv_bfloat16* srcs[4] = { s0, s1, s2, s3 };                    \
        _Pragma("unroll")                                                     \
        for (int a = 0; a < 4; a++) {                                         \
            const char* g0 = (const char*)(srcs[a] + (size_t)r0c * Kd + (kt) * KT) + c0c * 16; \
            const char* g1 = (const char*)(srcs[a] + (size_t)r1c * Kd + (kt) * KT) + c1c * 16; \
            uint32_t p0 = db + a * TILE_B + r0c * RB + c0c * 16;              \
            uint32_t p1 = db + a * TILE_B + r1c * RB + c1c * 16;              \
            asm volatile("cp.async.cg.shared.global [%0],[%1],16;" :: "r"(p0), "l"(g0)); \
            asm volatile("cp.async.cg.shared.global [%0],[%1],16;" :: "r"(p1), "l"(g1)); \
        }                                                                     \
        asm volatile("cp.async.commit_group;");                               \
    } while (0)

    float acc[4][4][4];
#pragma unroll
    for (int i = 0; i < 4; i++)
#pragma unroll
        for (int j = 0; j < 4; j++)
#pragma unroll
            for (int q = 0; q < 4; q++) acc[i][j][q] = 0.f;

    LOAD_STAGE(0, 0);
    int buf = 0;

    for (int kt = 0; kt < Kd / KT; kt++) {
        if (kt + 1 < Kd / KT) {
            LOAD_STAGE(kt + 1, buf ^ 1);
            asm volatile("cp.async.wait_group 1;");
        } else {
            asm volatile("cp.async.wait_group 0;");
        }
        __syncthreads();

        const uint32_t db = sbase + buf * STAGE_B;
#pragma unroll
        for (int ks = 0; ks < 2; ks++) {
            // A fragments (hi & lo), 4 m-frags each, ldmatrix x4
            uint32_t rah[4][4], ral[4][4];
#pragma unroll
            for (int mf = 0; mf < 4; mf++) {
                int r = wm * 64 + mf * 16 + (lane & 15);
                uint32_t ad = db + r * RB + ks * 32 + ((lane >> 4) & 1) * 16;
                asm volatile("ldmatrix.sync.aligned.m8n8.x4.shared.b16 {%0,%1,%2,%3},[%4];"
                    : "=r"(rah[mf][0]), "=r"(rah[mf][1]), "=r"(rah[mf][2]), "=r"(rah[mf][3])
                    : "r"(ad));
                asm volatile("ldmatrix.sync.aligned.m8n8.x4.shared.b16 {%0,%1,%2,%3},[%4];"
                    : "=r"(ral[mf][0]), "=r"(ral[mf][1]), "=r"(ral[mf][2]), "=r"(ral[mf][3])
                    : "r"(ad + TILE_B));
            }
            // B fragments (hi & lo), 4 n-frags each, ldmatrix x2
            uint32_t rbh[4][2], rbl[4][2];
#pragma unroll
            for (int nf = 0; nf < 4; nf++) {
                int r = wn * 32 + nf * 8 + (lane & 7);
                uint32_t bd = db + 2 * TILE_B + r * RB + ks * 32 + ((lane >> 3) & 1) * 16;
                asm volatile("ldmatrix.sync.aligned.m8n8.x2.shared.b16 {%0,%1},[%2];"
                    : "=r"(rbh[nf][0]), "=r"(rbh[nf][1]) : "r"(bd));
                asm volatile("ldmatrix.sync.aligned.m8n8.x2.shared.b16 {%0,%1},[%2];"
                    : "=r"(rbl[nf][0]), "=r"(rbl[nf][1]) : "r"(bd + TILE_B));
            }
#define MMA(d, A, Bf)                                                         \
    asm volatile("mma.sync.aligned.m16n8k16.row.col.f32.bf16.bf16.f32 "       \
                 "{%0,%1,%2,%3},{%4,%5,%6,%7},{%8,%9},{%0,%1,%2,%3};"         \
                 : "+f"(d[0]), "+f"(d[1]), "+f"(d[2]), "+f"(d[3])             \
                 : "r"(A[0]), "r"(A[1]), "r"(A[2]), "r"(A[3]),                \
                   "r"(Bf[0]), "r"(Bf[1]))
#pragma unroll
            for (int mf = 0; mf < 4; mf++)
#pragma unroll
                for (int nf = 0; nf < 4; nf++) {
                    MMA(acc[mf][nf], rah[mf], rbh[nf]);
                    MMA(acc[mf][nf], rah[mf], rbl[nf]);
                    MMA(acc[mf][nf], ral[mf], rbh[nf]);
                }
#undef MMA
        }
        __syncthreads();
        buf ^= 1;
    }

    // epilogue: fp32 stores, 2 floats per frag-row per thread
    const int mrow = lane >> 2, ncol = (lane & 3) * 2;
#pragma unroll
    for (int mf = 0; mf < 4; mf++) {
#pragma unroll
        for (int nf = 0; nf < 4; nf++) {
            int r  = row0 + wm * 64 + mf * 16 + mrow;
            int cc = col0 + wn * 32 + nf * 8 + ncol;
            *(float2*)(C + (size_t)r * N + cc) =
                make_float2(acc[mf][nf][0], acc[mf][nf][1]);
            *(float2*)(C + (size_t)(r + 8) * N + cc) =
                make_float2(acc[mf][nf][2], acc[mf][nf][3]);
        }
    }
#undef LOAD_STAGE
}

// ---------------------------------------------------------------------------
// fp32 -> bf16 hi/lo split, 4 elems/thread
// ---------------------------------------------------------------------------
__global__ void split_bf16(const float* __restrict__ s,
                           __nv_bfloat16* __restrict__ hi,
                           __nv_bfloat16* __restrict__ lo, int n4)
{
    int i = blockIdx.x * blockDim.x + threadIdx.x;
    if (i >= n4) return;
    float4 v = ((const float4*)s)[i];
    float vv[4] = { v.x, v.y, v.z, v.w };
    __nv_bfloat16 h[4], l[4];
#pragma unroll
    for (int j = 0; j < 4; j++) {
        h[j] = __float2bfloat16_rn(vv[j]);
        l[j] = __float2bfloat16_rn(vv[j] - __bfloat162float(h[j]));
    }
    ((__nv_bfloat162*)hi)[i * 2 + 0] = __halves2bfloat162(h[0], h[1]);
    ((__nv_bfloat162*)hi)[i * 2 + 1] = __halves2bfloat162(h[2], h[3]);
    ((__nv_bfloat162*)lo)[i * 2 + 0] = __halves2bfloat162(l[0], l[1]);
    ((__nv_bfloat162*)lo)[i * 2 + 1] = __halves2bfloat162(l[2], l[3]);
}

// ---------------------------------------------------------------------------
// qm = mean_t q[b,h,t,:] then tiny MLP -> pulse_widths[b,h]
// ---------------------------------------------------------------------------
__global__ __launch_bounds__(256) void qm_pulse_kernel(
    const float* __restrict__ W1, const float* __restrict__ b1,
    const float* __restrict__ W2, const float* __restrict__ b2,
    float* __restrict__ out_pulse)
{
    const int bh = blockIdx.x;
    const int b = bh >> 4, h = bh & 15;
    const int tid = threadIdx.x;
    const int d = tid & 63, chunk = tid >> 6;

    const float* base = g_qkv + (size_t)b * Tc * 3072 + h * 64 + d;
    float s = 0.f;
    const int t0 = chunk * 1024;
    for (int t = t0; t < t0 + 1024; t++)
        s += base[(size_t)t * 3072];

    __shared__ float part[256];
    __shared__ float qm[64];
    part[tid] = s;
    __syncthreads();
    if (tid < 64)
        qm[tid] = (part[tid] + part[tid + 64] + part[tid + 128] + part[tid + 192])
                  * (1.0f / Tc);
    __syncthreads();
    if (tid < 32) {
        float acc = b1[tid];
        for (int dd = 0; dd < 64; dd++)
            acc = fmaf(qm[dd], W1[tid * 64 + dd], acc);
        float h1 = acc / (1.f + expf(-acc));
        float p = h1 * W2[tid];
#pragma unroll
        for (int off = 16; off; off >>= 1)
            p += __shfl_down_sync(0xffffffffu, p, off);
        if (tid == 0) {
            float x = p + b2[0];
            float sp = (x > 20.f) ? x : log1pf(expf(x));
            out_pulse[bh] = 4.0f + sp;
        }
    }
}

// ---------------------------------------------------------------------------
// Spectral projection: spec_s[b,h,k,d] = sum_t qkv_s[b,h,t,d] * sb[b,t,k]
// ---------------------------------------------------------------------------
__global__ __launch_bounds__(256) void spec_kernel(const float* __restrict__ sb)
{
    const int bh = blockIdx.x, s = blockIdx.y;
    const int b = bh >> 4, h = bh & 15;
    const int tid = threadIdx.x;
    const int k = tid >> 3;
    const int d0 = (tid & 7) * 8;

    __shared__ float sbs[64][33];
    __shared__ float qs[64][65];
    float acc[8];
#pragma unroll
    for (int i = 0; i < 8; i++) acc[i] = 0.f;

    const float* qbase = g_qkv + (size_t)b * Tc * 3072 + s * 1024 + h * 64;
    const float* sbase = sb + (size_t)b * Tc * 32;

    for (int t0 = 0; t0 < Tc; t0 += 64) {
#pragma unroll
        for (int i = 0; i < 2; i++) {
            int e = tid + i * 256;
            int tt = e >> 3, k4 = (e & 7) * 4;
            float4 v = *(const float4*)(sbase + (size_t)(t0 + tt) * 32 + k4);
            sbs[tt][k4 + 0] = v.x; sbs[tt][k4 + 1] = v.y;
            sbs[tt][k4 + 2] = v.z; sbs[tt][k4 + 3] = v.w;
        }
#pragma unroll
        for (int i = 0; i < 4; i++) {
            int e = tid + i * 256;
            int tt = e >> 4, d4 = (e & 15) * 4;
            float4 v = *(const float4*)(qbase + (size_t)(t0 + tt) * 3072 + d4);
            qs[tt][d4 + 0] = v.x; qs[tt][d4 + 1] = v.y;
            qs[tt][d4 + 2] = v.z; qs[tt][d4 + 3] = v.w;
        }
        __syncthreads();
        for (int t = 0; t < 64; t++) {
            float sv = sbs[t][k];
#pragma unroll
            for (int i = 0; i < 8; i++)
                acc[i] = fmaf(sv, qs[t][d0 + i], acc[i]);
        }
        __syncthreads();
    }
    float* outp = g_spec + ((size_t)(s * (Bc * Hc) + bh) * Kc + k) * HDc + d0;
#pragma unroll
    for (int i = 0; i < 8; i++) outp[i] = acc[i];
}

// ---------------------------------------------------------------------------
// attn_spec + FitzHugh-Nagumo dynamics (constant along HD -> scalar ODE)
// ---------------------------------------------------------------------------
__global__ void soliton_kernel(
    const float* __restrict__ d_a, const float* __restrict__ d_b,
    const float* __restrict__ filt, float* __restrict__ out_resp)
{
    const int idx = blockIdx.x * blockDim.x + threadIdx.x;
    if (idx >= Bc * Hc * Kc) return;
    const int bh = idx >> 5, k = idx & 31;
    const int h = bh & 15;

    const size_t specN = (size_t)Bc * Hc * Kc * HDc;
    const float* qv = g_spec + (size_t)idx * 64;
    const float* kv = g_spec + specN + (size_t)idx * 64;
    float dot = 0.f;
#pragma unroll
    for (int d = 0; d < 64; d++) dot = fmaf(qv[d], kv[d], dot);

    float f = 1.f / (1.f + expf(-filt[h * 32 + k]));
    float stim = dot * 0.125f * f;

    const float a = d_a[0], bb = d_b[0];
    float scale = fmaxf(fabsf(stim), 1e-6f);
    float sn = stim / scale;
    float I = (fabsf(stim) > 0.5f) ? sn : sn * 0.1f;
    float v = 0.f, w = 0.f;
    const float dt = 0.2f;
#pragma unroll
    for (int s = 0; s < 5; s++) {
        float dv = v - v * v * v * (1.f / 3.f) - w + I;
        float dw = (v + a - bb * w) * 10.f;
        v = fminf(fmaxf(v + dt * dv, -3.f), 3.f);
        w = fminf(fmaxf(w + dt * dw, -3.f), 3.f);
    }
    float resp = v * scale;
    out_resp[idx] = resp;

    const float* vv = g_spec + 2 * specN + (size_t)idx * 64;
    float* ws = g_ws + (size_t)idx * 64;
#pragma unroll
    for (int d = 0; d < 64; d++) ws[d] = resp * vv[d];
}

// ---------------------------------------------------------------------------
// Recombine: mid[b,t,h*64+d] = sum_k sb[b,t,k] * ws[b,h,k,d] -> bf16 hi/lo
// ---------------------------------------------------------------------------
__global__ __launch_bounds__(256) void recombine_kernel(const float* __restrict__ sb)
{
    const int bh = blockIdx.x;
    const int b = bh >> 4, h = bh & 15;
    const int t0 = blockIdx.y * 128;
    const int tid = threadIdx.x;

    __shared__ float ws_s[32][65];
    __shared__ float sbs[128][33];

#pragma unroll
    for (int i = 0; i < 2; i++) {
        int e = tid + i * 256;
        int kk = e >> 4, d4 = (e & 15) * 4;
        float4 v = *(const float4*)(g_ws + ((size_t)bh * 32 + kk) * 64 + d4);
        ws_s[kk][d4 + 0] = v.x; ws_s[kk][d4 + 1] = v.y;
        ws_s[kk][d4 + 2] = v.z; ws_s[kk][d4 + 3] = v.w;
    }
    const float* sbase = sb + (size_t)b * Tc * 32;
#pragma unroll
    for (int i = 0; i < 4; i++) {
        int e = tid + i * 256;
        int tt = e >> 3, k4 = (e & 7) * 4;
        float4 v = *(const float4*)(sbase + (size_t)(t0 + tt) * 32 + k4);
        sbs[tt][k4 + 0] = v.x; sbs[tt][k4 + 1] = v.y;
        sbs[tt][k4 + 2] = v.z; sbs[tt][k4 + 3] = v.w;
    }
    __syncthreads();

    for (int e = tid; e < 128 * 64; e += 256) {
        int t = e >> 6, d = e & 63;
        float acc = 0.f;
#pragma unroll
        for (int k = 0; k < 32; k++)
            acc = fmaf(sbs[t][k], ws_s[k][d], acc);
        size_t oi = (size_t)(b * Tc + t0 + t) * Dc + h * 64 + d;
        __nv_bfloat16 hh = __float2bfloat16_rn(acc);
        g_mhi[oi] = hh;
        g_mlo[oi] = __float2bfloat16_rn(acc - __bfloat162float(hh));
    }
}

// ---------------------------------------------------------------------------
// Launch
// ---------------------------------------------------------------------------
extern "C" void kernel_launch(void* const* d_in, const int* in_sizes, int n_in,
                              void* d_out, int out_size)
{
    const float* x    = (const float*)d_in[0];
    const float* sb   = (const float*)d_in[1];
    const float* Wqkv = (const float*)d_in[2];
    const float* Wout = (const float*)d_in[3];
    const float* a    = (const float*)d_in[4];
    const float* b    = (const float*)d_in[5];
    const float* W1   = (const float*)d_in[6];
    const float* b1   = (const float*)d_in[7];
    const float* W2   = (const float*)d_in[8];
    const float* b2   = (const float*)d_in[9];
    const float* filt = (const float*)d_in[10];

    float* out       = (float*)d_out;
    float* out_pulse = out + (size_t)Bc * Tc * Dc;
    float* out_resp  = out_pulse + Bc * Hc;

    float* pqkv = nullptr;
    cudaGetSymbolAddress((void**)&pqkv, g_qkv);
    __nv_bfloat16 *pxhi, *pxlo, *pwqhi, *pwqlo, *pwohi, *pwolo, *pmhi, *pmlo;
    cudaGetSymbolAddress((void**)&pxhi, g_xhi);
    cudaGetSymbolAddress((void**)&pxlo, g_xlo);
    cudaGetSymbolAddress((void**)&pwqhi, g_wqhi);
    cudaGetSymbolAddress((void**)&pwqlo, g_wqlo);
    cudaGetSymbolAddress((void**)&pwohi, g_wohi);
    cudaGetSymbolAddress((void**)&pwolo, g_wolo);
    cudaGetSymbolAddress((void**)&pmhi, g_mhi);
    cudaGetSymbolAddress((void**)&pmlo, g_mlo);

    const int GEMM_SMEM = 2 * STAGE_B;   // 81920 B
    cudaFuncSetAttribute(gemm_mma, cudaFuncAttributeMaxDynamicSharedMemorySize, GEMM_SMEM);

    // 0) bf16 hi/lo splits
    {
        int n4 = (Bc * Tc * Dc) / 4;
        split_bf16<<<(n4 + 255) / 256, 256>>>(x, pxhi, pxlo, n4);
        n4 = (3 * Dc * Dc) / 4;
        split_bf16<<<(n4 + 255) / 256, 256>>>(Wqkv, pwqhi, pwqlo, n4);
        n4 = (Dc * Dc) / 4;
        split_bf16<<<(n4 + 255) / 256, 256>>>(Wout, pwohi, pwolo, n4);
    }

    // 1) QKV projection: (16384 x 1024) @ (3072 x 1024)^T  [mma.sync bf16]
    gemm_mma<<<dim3(3 * Dc / 128, Bc * Tc / 128), 256, GEMM_SMEM>>>(
        pxhi, pxlo, pwqhi, pwqlo, pqkv, Bc * Tc, 3 * Dc);

    // 2) Pulse widths
    qm_pulse_kernel<<<Bc * Hc, 256>>>(W1, b1, W2, b2, out_pulse);

    // 3) Spectral projections q/k/v
    spec_kernel<<<dim3(Bc * Hc, 3), 256>>>(sb);

    // 4) soliton dynamics + ws
    soliton_kernel<<<(Bc * Hc * Kc + 255) / 256, 256>>>(a, b, filt, out_resp);

    // 5) Recombine -> mid (bf16 hi/lo)
    recombine_kernel<<<dim3(Bc * Hc, Tc / 128), 256>>>(sb);

    // 6) Output projection: (16384 x 1024) @ (1024 x 1024)^T  [mma.sync bf16]
    gemm_mma<<<dim3(Dc / 128, Bc * Tc / 128), 256, GEMM_SMEM>>>(
        pmhi, pmlo, pwohi, pwolo, out, Bc * Tc, Dc);
}